// round 3
// baseline (speedup 1.0000x reference)
#include <cuda_runtime.h>

// DyDepthwiseConvAtten: fused dynamic-kernel depthwise conv + LayerNorm.
// B=1024, N=100, C=256, K=3. One CTA per (b,n) row, 256 threads (1/channel).
//
// out[c] = LN( v[c-1]*w0 + v[c]*w1 + v[c+1]*w2 ), w_k = sum_c q[c]*W_w[k][c] + b_w[k]

#define C_DIM 256
#define K_DIM 3
#define LN_EPS 1e-5f

__global__ __launch_bounds__(C_DIM, 8)
void dydwconv_ln_kernel(const float* __restrict__ q,
                        const float* __restrict__ v,
                        const float* __restrict__ Ww,     // [3, 256]
                        const float* __restrict__ bw,     // [3]
                        const float* __restrict__ gamma,  // [256]
                        const float* __restrict__ beta,   // [256]
                        float* __restrict__ out)
{
    const int row = blockIdx.x;              // b*N + n
    const int c   = threadIdx.x;             // channel
    const size_t base = (size_t)row * C_DIM;

    __shared__ float sv[C_DIM + 2];          // value row with zero halo
    __shared__ float wred[3][8];             // per-warp partials for w0,w1,w2
    __shared__ float mred[2][8];             // per-warp partials for mean/sumsq

    const float qc = q[base + c];
    const float vc = v[base + c];
    sv[c + 1] = vc;
    if (c == 0) { sv[0] = 0.0f; sv[C_DIM + 1] = 0.0f; }

    // ---- dynamic kernel: w_k = sum_c q[c] * Ww[k][c]  (fused 3-way reduction)
    float p0 = qc * Ww[c];
    float p1 = qc * Ww[C_DIM + c];
    float p2 = qc * Ww[2 * C_DIM + c];
    #pragma unroll
    for (int off = 16; off > 0; off >>= 1) {
        p0 += __shfl_xor_sync(0xFFFFFFFFu, p0, off);
        p1 += __shfl_xor_sync(0xFFFFFFFFu, p1, off);
        p2 += __shfl_xor_sync(0xFFFFFFFFu, p2, off);
    }
    const int warp = c >> 5;
    const int lane = c & 31;
    if (lane == 0) { wred[0][warp] = p0; wred[1][warp] = p1; wred[2][warp] = p2; }
    __syncthreads();   // also publishes sv[]

    float w0 = bw[0], w1 = bw[1], w2 = bw[2];
    #pragma unroll
    for (int i = 0; i < 8; i++) {
        w0 += wred[0][i];
        w1 += wred[1][i];
        w2 += wred[2][i];
    }

    // ---- depthwise conv along channel axis (zero-padded, K=3)
    const float o = sv[c] * w0 + sv[c + 1] * w1 + sv[c + 2] * w2;

    // ---- LayerNorm over C=256 (fused sum + sumsq reduction)
    float s  = o;
    float ss = o * o;
    #pragma unroll
    for (int off = 16; off > 0; off >>= 1) {
        s  += __shfl_xor_sync(0xFFFFFFFFu, s,  off);
        ss += __shfl_xor_sync(0xFFFFFFFFu, ss, off);
    }
    if (lane == 0) { mred[0][warp] = s; mred[1][warp] = ss; }
    __syncthreads();

    float tot = 0.0f, tot2 = 0.0f;
    #pragma unroll
    for (int i = 0; i < 8; i++) {
        tot  += mred[0][i];
        tot2 += mred[1][i];
    }
    const float mean = tot  * (1.0f / C_DIM);
    const float var  = tot2 * (1.0f / C_DIM) - mean * mean;
    const float inv  = rsqrtf(var + LN_EPS);

    out[base + c] = (o - mean) * inv * gamma[c] + beta[c];
}

extern "C" void kernel_launch(void* const* d_in, const int* in_sizes, int n_in,
                              void* d_out, int out_size)
{
    const float* q     = (const float*)d_in[0];
    const float* v     = (const float*)d_in[1];
    const float* Ww    = (const float*)d_in[2];
    const float* bw    = (const float*)d_in[3];
    const float* gamma = (const float*)d_in[4];
    const float* beta  = (const float*)d_in[5];
    float* out = (float*)d_out;

    const int rows = in_sizes[0] / C_DIM;    // B*N = 102400
    dydwconv_ln_kernel<<<rows, C_DIM>>>(q, v, Ww, bw, gamma, beta, out);
}

// round 4
// speedup vs baseline: 3.6709x; 3.6709x over previous
#include <cuda_runtime.h>

// DyDepthwiseConvAtten fused: dynamic 3-tap depthwise conv along C + LayerNorm.
// B*N = 102400 rows, C = 256. Warp-per-row, 8 channels per lane (2x float4).
// All reductions are warp shuffles; constants (Ww, bw, gamma, beta) live in
// registers and are amortized over a grid-stride row loop.

#define C_DIM  256
#define LN_EPS 1e-5f
#define FULL   0xFFFFFFFFu

__global__ __launch_bounds__(256)
void dydwconv_ln_kernel(const float* __restrict__ q,
                        const float* __restrict__ v,
                        const float* __restrict__ Ww,     // [3,256]
                        const float* __restrict__ bw,     // [3]
                        const float* __restrict__ gamma,  // [256]
                        const float* __restrict__ beta,   // [256]
                        float* __restrict__ out,
                        int rows, int total_warps)
{
    const int warp_g = (blockIdx.x * blockDim.x + threadIdx.x) >> 5;
    const int lane   = threadIdx.x & 31;
    const int cbase  = lane * 8;               // first channel owned by this lane

    // ---- hoisted constants (registers) ----
    float W0[8], W1[8], W2[8], G[8], Bt[8];
    {
        const float4* p;
        p = (const float4*)(Ww + 0 * C_DIM + cbase);
        float4 a = p[0], b = p[1];
        W0[0]=a.x; W0[1]=a.y; W0[2]=a.z; W0[3]=a.w; W0[4]=b.x; W0[5]=b.y; W0[6]=b.z; W0[7]=b.w;
        p = (const float4*)(Ww + 1 * C_DIM + cbase);
        a = p[0]; b = p[1];
        W1[0]=a.x; W1[1]=a.y; W1[2]=a.z; W1[3]=a.w; W1[4]=b.x; W1[5]=b.y; W1[6]=b.z; W1[7]=b.w;
        p = (const float4*)(Ww + 2 * C_DIM + cbase);
        a = p[0]; b = p[1];
        W2[0]=a.x; W2[1]=a.y; W2[2]=a.z; W2[3]=a.w; W2[4]=b.x; W2[5]=b.y; W2[6]=b.z; W2[7]=b.w;
        p = (const float4*)(gamma + cbase);
        a = p[0]; b = p[1];
        G[0]=a.x; G[1]=a.y; G[2]=a.z; G[3]=a.w; G[4]=b.x; G[5]=b.y; G[6]=b.z; G[7]=b.w;
        p = (const float4*)(beta + cbase);
        a = p[0]; b = p[1];
        Bt[0]=a.x; Bt[1]=a.y; Bt[2]=a.z; Bt[3]=a.w; Bt[4]=b.x; Bt[5]=b.y; Bt[6]=b.z; Bt[7]=b.w;
    }
    const float bw0 = bw[0], bw1 = bw[1], bw2 = bw[2];

    for (int row = warp_g; row < rows; row += total_warps) {
        const size_t base = (size_t)row * C_DIM + cbase;

        float Q[8], V[8];
        {
            const float4* qp = (const float4*)(q + base);
            float4 a = qp[0], b = qp[1];
            Q[0]=a.x; Q[1]=a.y; Q[2]=a.z; Q[3]=a.w; Q[4]=b.x; Q[5]=b.y; Q[6]=b.z; Q[7]=b.w;
            const float4* vp = (const float4*)(v + base);
            a = vp[0]; b = vp[1];
            V[0]=a.x; V[1]=a.y; V[2]=a.z; V[3]=a.w; V[4]=b.x; V[5]=b.y; V[6]=b.z; V[7]=b.w;
        }

        // ---- dynamic kernel weights: w_k = bw[k] + sum_c q[c]*Ww[k][c] ----
        float p0 = 0.f, p1 = 0.f, p2 = 0.f;
        #pragma unroll
        for (int i = 0; i < 8; i++) {
            p0 = fmaf(Q[i], W0[i], p0);
            p1 = fmaf(Q[i], W1[i], p1);
            p2 = fmaf(Q[i], W2[i], p2);
        }
        #pragma unroll
        for (int off = 16; off > 0; off >>= 1) {
            p0 += __shfl_xor_sync(FULL, p0, off);
            p1 += __shfl_xor_sync(FULL, p1, off);
            p2 += __shfl_xor_sync(FULL, p2, off);
        }
        const float w0 = bw0 + p0;
        const float w1 = bw1 + p1;
        const float w2 = bw2 + p2;

        // ---- halo exchange for 3-tap conv (zero padded) ----
        float vl = __shfl_up_sync(FULL, V[7], 1);    // channel cbase-1
        float vr = __shfl_down_sync(FULL, V[0], 1);  // channel cbase+8
        if (lane == 0)  vl = 0.f;
        if (lane == 31) vr = 0.f;

        float O[8];
        O[0] = vl * w0 + V[0] * w1 + V[1] * w2;
        #pragma unroll
        for (int i = 1; i < 7; i++)
            O[i] = V[i - 1] * w0 + V[i] * w1 + V[i + 1] * w2;
        O[7] = V[6] * w0 + V[7] * w1 + vr * w2;

        // ---- LayerNorm over 256 channels ----
        float s = 0.f, ss = 0.f;
        #pragma unroll
        for (int i = 0; i < 8; i++) {
            s += O[i];
            ss = fmaf(O[i], O[i], ss);
        }
        #pragma unroll
        for (int off = 16; off > 0; off >>= 1) {
            s  += __shfl_xor_sync(FULL, s,  off);
            ss += __shfl_xor_sync(FULL, ss, off);
        }
        const float mean = s  * (1.0f / C_DIM);
        const float var  = ss * (1.0f / C_DIM) - mean * mean;
        const float inv  = rsqrtf(var + LN_EPS);

        float4 o0, o1;
        o0.x = (O[0] - mean) * inv * G[0] + Bt[0];
        o0.y = (O[1] - mean) * inv * G[1] + Bt[1];
        o0.z = (O[2] - mean) * inv * G[2] + Bt[2];
        o0.w = (O[3] - mean) * inv * G[3] + Bt[3];
        o1.x = (O[4] - mean) * inv * G[4] + Bt[4];
        o1.y = (O[5] - mean) * inv * G[5] + Bt[5];
        o1.z = (O[6] - mean) * inv * G[6] + Bt[6];
        o1.w = (O[7] - mean) * inv * G[7] + Bt[7];
        float4* op = (float4*)(out + base);
        op[0] = o0;
        op[1] = o1;
    }
}

extern "C" void kernel_launch(void* const* d_in, const int* in_sizes, int n_in,
                              void* d_out, int out_size)
{
    const float* q     = (const float*)d_in[0];
    const float* v     = (const float*)d_in[1];
    const float* Ww    = (const float*)d_in[2];
    const float* bw    = (const float*)d_in[3];
    const float* gamma = (const float*)d_in[4];
    const float* beta  = (const float*)d_in[5];
    float* out = (float*)d_out;

    const int rows = in_sizes[0] / C_DIM;        // 102400
    const int grid = 1184;                       // 148 SMs * 8 CTAs
    const int total_warps = grid * (256 / 32);   // 9472 -> ~10.8 rows/warp
    dydwconv_ln_kernel<<<grid, 256>>>(q, v, Ww, bw, gamma, beta, out,
                                      rows, total_warps);
}

// round 5
// speedup vs baseline: 3.6730x; 1.0006x over previous
#include <cuda_runtime.h>

// DyDepthwiseConvAtten fused: dynamic 3-tap depthwise conv along C + LayerNorm.
// B*N = 102400 rows, C = 256. Warp-per-row, 8 channels/lane (2x float4).
// R4: constants live in conflict-free SMEM ([i][lane] layout) to cut register
// pressure (occ 3->4 CTAs/SM), plus one-deep prefetch of the next row's Q/V
// to overlap DRAM latency with the shuffle-reduction chains.

#define C_DIM  256
#define LN_EPS 1e-5f
#define FULL   0xFFFFFFFFu

__global__ __launch_bounds__(256, 4)
void dydwconv_ln_kernel(const float* __restrict__ q,
                        const float* __restrict__ v,
                        const float* __restrict__ Ww,     // [3,256]
                        const float* __restrict__ bw,     // [3]
                        const float* __restrict__ gamma,  // [256]
                        const float* __restrict__ beta,   // [256]
                        float* __restrict__ out,
                        int rows, int total_warps)
{
    // constants, transposed so sW[k][i][lane] = const_k[channel = lane*8+i]
    // address for fixed (k,i) is i*32+lane -> bank == lane -> conflict-free
    __shared__ float sW[5][8][32];

    const int tid  = threadIdx.x;
    const int lane = tid & 31;
    {
        const int i  = tid >> 5;          // 0..7
        const int ch = lane * 8 + i;      // channel this slot describes
        sW[0][i][lane] = Ww[ch];
        sW[1][i][lane] = Ww[C_DIM + ch];
        sW[2][i][lane] = Ww[2 * C_DIM + ch];
        sW[3][i][lane] = gamma[ch];
        sW[4][i][lane] = beta[ch];
    }
    __syncthreads();

    const float bw0 = bw[0], bw1 = bw[1], bw2 = bw[2];

    const int warp_g = (blockIdx.x * blockDim.x + tid) >> 5;
    const int cbase  = lane * 8;

    if (warp_g >= rows) return;

    // ---- prefetch first row ----
    size_t base = (size_t)warp_g * C_DIM + cbase;
    float4 qa = ((const float4*)(q + base))[0];
    float4 qb = ((const float4*)(q + base))[1];
    float4 va = ((const float4*)(v + base))[0];
    float4 vb = ((const float4*)(v + base))[1];

    for (int row = warp_g; row < rows; row += total_warps) {
        // ---- issue next row's loads early (clamped address, always valid) ----
        const int nrow = row + total_warps;
        const int crow = nrow < rows ? nrow : rows - 1;
        const size_t nbase = (size_t)crow * C_DIM + cbase;
        const float4 nqa = ((const float4*)(q + nbase))[0];
        const float4 nqb = ((const float4*)(q + nbase))[1];
        const float4 nva = ((const float4*)(v + nbase))[0];
        const float4 nvb = ((const float4*)(v + nbase))[1];

        float Q[8] = {qa.x, qa.y, qa.z, qa.w, qb.x, qb.y, qb.z, qb.w};
        float V[8] = {va.x, va.y, va.z, va.w, vb.x, vb.y, vb.z, vb.w};

        // ---- dynamic kernel weights: w_k = bw[k] + sum_c q[c]*Ww[k][c] ----
        float p0 = 0.f, p1 = 0.f, p2 = 0.f;
        #pragma unroll
        for (int i = 0; i < 8; i++) {
            p0 = fmaf(Q[i], sW[0][i][lane], p0);
            p1 = fmaf(Q[i], sW[1][i][lane], p1);
            p2 = fmaf(Q[i], sW[2][i][lane], p2);
        }
        #pragma unroll
        for (int off = 16; off > 0; off >>= 1) {
            p0 += __shfl_xor_sync(FULL, p0, off);
            p1 += __shfl_xor_sync(FULL, p1, off);
            p2 += __shfl_xor_sync(FULL, p2, off);
        }
        const float w0 = bw0 + p0;
        const float w1 = bw1 + p1;
        const float w2 = bw2 + p2;

        // ---- halo exchange for 3-tap conv (zero padded) ----
        float vl = __shfl_up_sync(FULL, V[7], 1);    // channel cbase-1
        float vr = __shfl_down_sync(FULL, V[0], 1);  // channel cbase+8
        if (lane == 0)  vl = 0.f;
        if (lane == 31) vr = 0.f;

        float O[8];
        O[0] = vl * w0 + V[0] * w1 + V[1] * w2;
        #pragma unroll
        for (int i = 1; i < 7; i++)
            O[i] = V[i - 1] * w0 + V[i] * w1 + V[i + 1] * w2;
        O[7] = V[6] * w0 + V[7] * w1 + vr * w2;

        // ---- LayerNorm over 256 channels ----
        float s = 0.f, ss = 0.f;
        #pragma unroll
        for (int i = 0; i < 8; i++) {
            s += O[i];
            ss = fmaf(O[i], O[i], ss);
        }
        #pragma unroll
        for (int off = 16; off > 0; off >>= 1) {
            s  += __shfl_xor_sync(FULL, s,  off);
            ss += __shfl_xor_sync(FULL, ss, off);
        }
        const float mean = s  * (1.0f / C_DIM);
        const float var  = ss * (1.0f / C_DIM) - mean * mean;
        const float inv  = rsqrtf(var + LN_EPS);

        float4 o0, o1;
        o0.x = (O[0] - mean) * inv * sW[3][0][lane] + sW[4][0][lane];
        o0.y = (O[1] - mean) * inv * sW[3][1][lane] + sW[4][1][lane];
        o0.z = (O[2] - mean) * inv * sW[3][2][lane] + sW[4][2][lane];
        o0.w = (O[3] - mean) * inv * sW[3][3][lane] + sW[4][3][lane];
        o1.x = (O[4] - mean) * inv * sW[3][4][lane] + sW[4][4][lane];
        o1.y = (O[5] - mean) * inv * sW[3][5][lane] + sW[4][5][lane];
        o1.z = (O[6] - mean) * inv * sW[3][6][lane] + sW[4][6][lane];
        o1.w = (O[7] - mean) * inv * sW[3][7][lane] + sW[4][7][lane];
        float4* op = (float4*)(out + base);
        op[0] = o0;
        op[1] = o1;

        // ---- rotate prefetch buffers ----
        base = nbase;
        qa = nqa; qb = nqb; va = nva; vb = nvb;
    }
}

extern "C" void kernel_launch(void* const* d_in, const int* in_sizes, int n_in,
                              void* d_out, int out_size)
{
    const float* q     = (const float*)d_in[0];
    const float* v     = (const float*)d_in[1];
    const float* Ww    = (const float*)d_in[2];
    const float* bw    = (const float*)d_in[3];
    const float* gamma = (const float*)d_in[4];
    const float* beta  = (const float*)d_in[5];
    float* out = (float*)d_out;

    const int rows = in_sizes[0] / C_DIM;        // 102400
    const int grid = 592;                        // 148 SMs * 4 CTAs (one wave)
    const int total_warps = grid * (256 / 32);   // 4736 -> ~21.6 rows/warp
    dydwconv_ln_kernel<<<grid, 256>>>(q, v, Ww, bw, gamma, beta, out,
                                      rows, total_warps);
}